// round 8
// baseline (speedup 1.0000x reference)
#include <cuda_runtime.h>
#include <cuda_bf16.h>
#include <cstdint>

// Output pattern, shape [2, G*N*N] flattened row-major, FLOAT32 values:
//   half 0: out[g*N*N + i]     = float(i / N)   (row index)
//   half 1: out[H + g*N*N + i] = float(i % N)   (col index),  H = G*N*N
// Pure write-only stream (512 MiB for N=4096, G=4); inputs' values unused.
//
// Lessons: (R4) per-STG warp footprint must be a contiguous fully-covered 2KB
// span; (R5-R7) we sit at the HBM write ceiling (~7.47 TB/s achieved), and
// the 2KB-grain L2 address hash makes burst-locality tricks beyond 2KB moot.
// This version removes the last non-bandwidth cost: a persistent grid
// (2048 blocks, grid-stride over 2*G*N row-units) kills wave-transition and
// tiny-CTA tail overhead of the previous 32768-block launch.

// Fast path: N % (256*4) == 0. Work unit u in [0, 2*G*N):
//   half = u / (G*N); g = (u % (G*N)) / N; r = u % N.
// Each unit writes one 16KB row of one half as a pure sequential stream.
__global__ void fa_persist_kernel(float* __restrict__ out,
                                  unsigned N, unsigned G,
                                  long long halfElems) {
    const unsigned GN = G * N;
    const unsigned totalUnits = 2u * GN;
    const long long NNll = (long long)N * (long long)N;
    const unsigned stride = blockDim.x * 4u;       // 1024 floats
    const unsigned iters = N / stride;             // 4 for N=4096, 256 thr
    const unsigned t4 = threadIdx.x * 4u;

    for (unsigned u = blockIdx.x; u < totalUnits; u += gridDim.x) {
        const bool colHalf = (u >= GN);
        const unsigned rem = colHalf ? (u - GN) : u;
        const unsigned g = rem / N;
        const unsigned r = rem - g * N;

        long long base = (colHalf ? halfElems : 0LL)
                       + (long long)g * NNll
                       + (long long)r * (long long)N
                       + (long long)t4;

        if (colHalf) {
            float c = (float)t4;
            for (unsigned j = 0; j < iters; j++) {
                __stcs(reinterpret_cast<float4*>(out + base),
                       make_float4(c, c + 1.0f, c + 2.0f, c + 3.0f));
                base += stride;
                c += (float)stride;
            }
        } else {
            const float rf = (float)r;
            const float4 rv = make_float4(rf, rf, rf, rf);
            for (unsigned j = 0; j < iters; j++) {
                __stcs(reinterpret_cast<float4*>(out + base), rv);
                base += stride;
            }
        }
    }
}

// Generic path: thread = one float4 per half, N % 4 == 0.
__global__ void fa_vec_kernel(float* __restrict__ out,
                              unsigned N, unsigned NN, long long halfElems) {
    unsigned i4 = ((unsigned)blockIdx.x * blockDim.x + threadIdx.x) * 4u;
    if (i4 >= NN) return;
    unsigned r = i4 / N;
    unsigned c = i4 - r * N;
    long long base = (long long)blockIdx.y * (long long)NN + (long long)i4;
    float rf = (float)r, cf = (float)c;
    __stcs(reinterpret_cast<float4*>(out + base),
           make_float4(rf, rf, rf, rf));
    __stcs(reinterpret_cast<float4*>(out + halfElems + base),
           make_float4(cf, cf + 1.0f, cf + 2.0f, cf + 3.0f));
}

// Scalar fallback.
__global__ void fa_scalar_kernel(float* __restrict__ out,
                                 unsigned N, unsigned NN, long long halfElems) {
    unsigned i = (unsigned)blockIdx.x * blockDim.x + threadIdx.x;
    if (i >= NN) return;
    unsigned r = i / N;
    unsigned c = i - r * N;
    long long base = (long long)blockIdx.y * (long long)NN + (long long)i;
    out[base] = (float)r;
    out[halfElems + base] = (float)c;
}

extern "C" void kernel_launch(void* const* d_in, const int* in_sizes, int n_in,
                              void* d_out, int out_size) {
    (void)d_in;
    // Derive N: the input size s with out_size == 2*G*s*s, integer 1<=G<=4096.
    long long N = 0, G = 0;
    for (int i = 0; i < n_in; i++) {
        long long s = (long long)in_sizes[i];
        if (s <= 0) continue;
        long long denom = 2LL * s * s;
        if (denom <= 0) continue;
        if ((long long)out_size % denom != 0) continue;
        long long g = (long long)out_size / denom;
        if (g >= 1 && g <= 4096) { N = s; G = g; break; }
    }
    if (N == 0) {
        N = (long long)in_sizes[2];
        long long denom = 2LL * N * N;
        G = (denom > 0 && (long long)out_size % denom == 0)
                ? (long long)out_size / denom : 1;
    }

    const long long NNll = N * N;
    const unsigned NN = (unsigned)NNll;
    const long long halfElems = G * NNll;
    float* out = (float*)d_out;
    const int threads = 256;

    if ((N % (threads * 4)) == 0 && 2 * G * N <= 0x7FFFFFFFLL) {
        const long long totalUnits = 2 * G * N;          // 32768 for default
        unsigned blocks = 2048;
        if ((long long)blocks > totalUnits) blocks = (unsigned)totalUnits;
        fa_persist_kernel<<<blocks, threads>>>(out, (unsigned)N, (unsigned)G,
                                               halfElems);
    } else if ((N % 4) == 0 && NNll <= 0xFFFFFFFFLL) {
        const unsigned elems4 = NN / 4u;
        unsigned gx = (elems4 + threads - 1) / threads;
        if (gx == 0) gx = 1;
        dim3 grid(gx, (unsigned)G, 1);
        fa_vec_kernel<<<grid, threads>>>(out, (unsigned)N, NN, halfElems);
    } else {
        unsigned gx = (unsigned)((NNll + threads - 1) / threads);
        if (gx == 0) gx = 1;
        dim3 grid(gx, (unsigned)G, 1);
        fa_scalar_kernel<<<grid, threads>>>(out, (unsigned)N, NN, halfElems);
    }
}

// round 9
// speedup vs baseline: 1.1072x; 1.1072x over previous
#include <cuda_runtime.h>
#include <cuda_bf16.h>
#include <cstdint>

// Output pattern, shape [2, G*N*N] flattened row-major, FLOAT32 values:
//   half 0: out[g*N*N + i]     = float(i / N)   (row index)
//   half 1: out[H + g*N*N + i] = float(i % N)   (col index),  H = G*N*N
// Pure write-only stream (512 MiB for N=4096, G=4); inputs' values unused.
//
// Final version (R7 shape — measured optimum across R3-R8):
//  - (R4) per-STG warp footprint = contiguous fully-covered 2KB span
//    (thread = one float4); wider per-thread tiling fractures 128B lines
//    and triggers L2/HBM read-modify-write (2x traffic, 2x time).
//  - (R8) persistent grid regresses: fresh small CTAs present more
//    outstanding-store pressure than a serial per-block unit loop.
//  - (R5-R7) we sit at the HBM write-stream ceiling (~7.45 TB/s achieved,
//    ~84% DRAM active); the 2KB-grain L2 address hash neutralizes further
//    burst-locality engineering.
//  - __stcs (evict-first): output is 4x L2 capacity and never re-read.

// Fast path: N % (256*4) == 0. grid = (1, N, 2G); z<G: row-half, z>=G: col-half.
// Each block writes ONE 16KB row of ONE half as a pure sequential stream.
__global__ void fa_row_split_kernel(float* __restrict__ out,
                                    unsigned N, unsigned G,
                                    long long halfElems) {
    const unsigned r = blockIdx.y;                 // row index
    const unsigned z = blockIdx.z;
    const bool colHalf = (z >= G);
    const unsigned g = colHalf ? (z - G) : z;
    const long long NNll = (long long)N * (long long)N;

    long long base = (colHalf ? halfElems : 0LL)
                   + (long long)g * NNll
                   + (long long)r * (long long)N
                   + (long long)(threadIdx.x * 4u);

    const unsigned stride = blockDim.x * 4u;       // 1024 floats
    const unsigned iters = N / stride;             // 4 for N=4096, 256 thr

    if (colHalf) {
        float c = (float)(threadIdx.x * 4u);
        for (unsigned j = 0; j < iters; j++) {
            __stcs(reinterpret_cast<float4*>(out + base),
                   make_float4(c, c + 1.0f, c + 2.0f, c + 3.0f));
            base += stride;
            c += (float)stride;
        }
    } else {
        const float rf = (float)r;
        const float4 rv = make_float4(rf, rf, rf, rf);
        for (unsigned j = 0; j < iters; j++) {
            __stcs(reinterpret_cast<float4*>(out + base), rv);
            base += stride;
        }
    }
}

// Generic path: thread = one float4 per half, N % 4 == 0.
__global__ void fa_vec_kernel(float* __restrict__ out,
                              unsigned N, unsigned NN, long long halfElems) {
    unsigned i4 = ((unsigned)blockIdx.x * blockDim.x + threadIdx.x) * 4u;
    if (i4 >= NN) return;
    unsigned r = i4 / N;
    unsigned c = i4 - r * N;
    long long base = (long long)blockIdx.y * (long long)NN + (long long)i4;
    float rf = (float)r, cf = (float)c;
    __stcs(reinterpret_cast<float4*>(out + base),
           make_float4(rf, rf, rf, rf));
    __stcs(reinterpret_cast<float4*>(out + halfElems + base),
           make_float4(cf, cf + 1.0f, cf + 2.0f, cf + 3.0f));
}

// Scalar fallback.
__global__ void fa_scalar_kernel(float* __restrict__ out,
                                 unsigned N, unsigned NN, long long halfElems) {
    unsigned i = (unsigned)blockIdx.x * blockDim.x + threadIdx.x;
    if (i >= NN) return;
    unsigned r = i / N;
    unsigned c = i - r * N;
    long long base = (long long)blockIdx.y * (long long)NN + (long long)i;
    out[base] = (float)r;
    out[halfElems + base] = (float)c;
}

extern "C" void kernel_launch(void* const* d_in, const int* in_sizes, int n_in,
                              void* d_out, int out_size) {
    (void)d_in;
    // Derive N: the input size s with out_size == 2*G*s*s, integer 1<=G<=4096.
    long long N = 0, G = 0;
    for (int i = 0; i < n_in; i++) {
        long long s = (long long)in_sizes[i];
        if (s <= 0) continue;
        long long denom = 2LL * s * s;
        if (denom <= 0) continue;
        if ((long long)out_size % denom != 0) continue;
        long long g = (long long)out_size / denom;
        if (g >= 1 && g <= 4096) { N = s; G = g; break; }
    }
    if (N == 0) {
        N = (long long)in_sizes[2];
        long long denom = 2LL * N * N;
        G = (denom > 0 && (long long)out_size % denom == 0)
                ? (long long)out_size / denom : 1;
    }

    const long long NNll = N * N;
    const unsigned NN = (unsigned)NNll;
    const long long halfElems = G * NNll;
    float* out = (float*)d_out;
    const int threads = 256;

    if ((N % (threads * 4)) == 0 && N <= 65535LL && 2 * G <= 65535LL) {
        dim3 grid(1, (unsigned)N, (unsigned)(2 * G));
        fa_row_split_kernel<<<grid, threads>>>(out, (unsigned)N, (unsigned)G,
                                               halfElems);
    } else if ((N % 4) == 0 && NNll <= 0xFFFFFFFFLL) {
        const unsigned elems4 = NN / 4u;
        unsigned gx = (elems4 + threads - 1) / threads;
        if (gx == 0) gx = 1;
        dim3 grid(gx, (unsigned)G, 1);
        fa_vec_kernel<<<grid, threads>>>(out, (unsigned)N, NN, halfElems);
    } else {
        unsigned gx = (unsigned)((NNll + threads - 1) / threads);
        if (gx == 0) gx = 1;
        dim3 grid(gx, (unsigned)G, 1);
        fa_scalar_kernel<<<grid, threads>>>(out, (unsigned)N, NN, halfElems);
    }
}